// round 1
// baseline (speedup 1.0000x reference)
#include <cuda_runtime.h>
#include <cuda_bf16.h>
#include <cstdint>

// Problem constants
#define BD 8
#define SD 2048
#define DD 1024
#define HD 1024
#define ED 2048            // 2H
#define MD (BD * SD)       // 16384 rows
#define LAYERS 4

// Scratch (allocation-free rule: device globals)
__device__ float g_gh[(size_t)MD * ED];      // (B*S, 2H) pre-activations
__device__ float g_bufA[(size_t)MD * HD];    // ping
__device__ float g_bufB[(size_t)MD * HD];    // pong

// ---------------------------------------------------------------------------
// GEMM: C[m,e] = sum_k A[m,k] * W[e,k] + bias[e]
// A: (MD, DD) row-major; W: (ED, DD) row-major (both K-contiguous, "NT" gemm)
// 128x128 block tile, K-step 8, 8x8 per thread, 256 threads, light pipelining.
// ---------------------------------------------------------------------------
__global__ __launch_bounds__(256) void gemm_k(
    const float* __restrict__ A,
    const float* __restrict__ W,
    const float* __restrict__ bias,
    float* __restrict__ C)
{
    __shared__ float As[8][132];   // padded to avoid store-phase bank conflicts
    __shared__ float Bs[8][132];

    const int tid = threadIdx.x;
    const int bm = blockIdx.y * 128;
    const int bn = blockIdx.x * 128;

    // tile-load mapping: 256 threads x 1 float4 each = 128 rows x 8 k
    const int lr = tid >> 1;            // 0..127
    const int lc = (tid & 1) << 2;      // 0 or 4
    const float* Ap = A + (size_t)(bm + lr) * DD + lc;
    const float* Wp = W + (size_t)(bn + lr) * DD + lc;

    // compute mapping: 16x16 thread grid, 8x8 each
    const int tm = (tid >> 4) << 3;
    const int tn = (tid & 15) << 3;

    float acc[8][8];
#pragma unroll
    for (int i = 0; i < 8; i++)
#pragma unroll
        for (int j = 0; j < 8; j++) acc[i][j] = 0.f;

    float4 av = *(const float4*)(Ap);
    float4 wv = *(const float4*)(Wp);

    for (int k0 = 0; k0 < DD; k0 += 8) {
        As[lc + 0][lr] = av.x; As[lc + 1][lr] = av.y;
        As[lc + 2][lr] = av.z; As[lc + 3][lr] = av.w;
        Bs[lc + 0][lr] = wv.x; Bs[lc + 1][lr] = wv.y;
        Bs[lc + 2][lr] = wv.z; Bs[lc + 3][lr] = wv.w;
        __syncthreads();

        if (k0 + 8 < DD) {   // prefetch next tile while computing
            av = *(const float4*)(Ap + k0 + 8);
            wv = *(const float4*)(Wp + k0 + 8);
        }

#pragma unroll
        for (int kk = 0; kk < 8; kk++) {
            float af[8], bf[8];
            const float4 a0 = *(const float4*)&As[kk][tm];
            const float4 a1 = *(const float4*)&As[kk][tm + 4];
            const float4 b0 = *(const float4*)&Bs[kk][tn];
            const float4 b1 = *(const float4*)&Bs[kk][tn + 4];
            af[0]=a0.x; af[1]=a0.y; af[2]=a0.z; af[3]=a0.w;
            af[4]=a1.x; af[5]=a1.y; af[6]=a1.z; af[7]=a1.w;
            bf[0]=b0.x; bf[1]=b0.y; bf[2]=b0.z; bf[3]=b0.w;
            bf[4]=b1.x; bf[5]=b1.y; bf[6]=b1.z; bf[7]=b1.w;
#pragma unroll
            for (int i = 0; i < 8; i++)
#pragma unroll
                for (int j = 0; j < 8; j++)
                    acc[i][j] = fmaf(af[i], bf[j], acc[i][j]);
        }
        __syncthreads();
    }

    // epilogue: add bias, store
    float bvals[8];
#pragma unroll
    for (int j = 0; j < 8; j++) bvals[j] = bias[bn + tn + j];

#pragma unroll
    for (int i = 0; i < 8; i++) {
        float* Cp = C + (size_t)(bm + tm + i) * ED + bn + tn;
        float4 v0, v1;
        v0.x = acc[i][0] + bvals[0]; v0.y = acc[i][1] + bvals[1];
        v0.z = acc[i][2] + bvals[2]; v0.w = acc[i][3] + bvals[3];
        v1.x = acc[i][4] + bvals[4]; v1.y = acc[i][5] + bvals[5];
        v1.z = acc[i][6] + bvals[6]; v1.w = acc[i][7] + bvals[7];
        *(float4*)(Cp)     = v0;
        *(float4*)(Cp + 4) = v1;
    }
}

// ---------------------------------------------------------------------------
// Scan: h_t = (1-z_t) h_{t-1} + z_t g(hid_t),  z = sigmoid(gate),
//       g(x) = x+0.5 (x>=0) else sigmoid(x);  h_0 = g(h_prev).
// out[b,t,h] = h_t + inp[b,t,h]  (residual);  finals[b,h] = h_{S-1} pre-residual.
// Block = (32 h-lanes) x (8 t-chunks of 256). 3-phase chunked parallel scan.
// ---------------------------------------------------------------------------
__device__ __forceinline__ float sigmoidf_fast(float x) {
    return 1.0f / (1.0f + __expf(-x));
}

__global__ __launch_bounds__(256) void scan_k(
    const float* __restrict__ gh,     // (B*S, 2H)
    const float* __restrict__ inp,    // (B*S, H) residual input
    const float* __restrict__ h0,     // (B, H) layer's h_prev
    float* __restrict__ outp,         // (B*S, H)
    float* __restrict__ finals)       // (B, H)
{
    const int b  = blockIdx.y;
    const int hx = threadIdx.x & 31;
    const int tc = threadIdx.x >> 5;
    const int h  = blockIdx.x * 32 + hx;
    const int CH = SD / 8;            // 256 steps per thread
    const int t0 = tc * CH;

    const size_t rowbase = (size_t)b * SD;
    const float* gp  = gh + rowbase * ED + h;        // gate stream
    const float* hp_ = gp + HD;                      // hidden stream

    // phase 1: per-chunk composite (A, C): h_end = A*h_start + C
    float Ac = 1.f, Cc = 0.f;
    for (int j = 0; j < CH; j++) {
        const size_t off = (size_t)(t0 + j) * ED;
        const float gate = gp[off];
        const float hid  = hp_[off];
        const float z = sigmoidf_fast(gate);
        const float g = (hid >= 0.f) ? (hid + 0.5f) : sigmoidf_fast(hid);
        const float a = 1.f - z;
        Cc = fmaf(a, Cc, z * g);
        Ac *= a;
    }

    __shared__ float sA[8][33], sC[8][33];
    sA[tc][hx] = Ac; sC[tc][hx] = Cc;
    __syncthreads();

    // phase 2: serial combine of <=7 prior chunks (tiny)
    const float hprev = h0[b * HD + h];
    float hcur = (hprev >= 0.f) ? (hprev + 0.5f) : sigmoidf_fast(hprev);
    for (int c = 0; c < tc; c++)
        hcur = fmaf(sA[c][hx], hcur, sC[c][hx]);

    // phase 3: replay, write out + residual
    const float* ip = inp + rowbase * HD + h;
    float* op       = outp + rowbase * HD + h;
    for (int j = 0; j < CH; j++) {
        const size_t off = (size_t)(t0 + j) * ED;
        const float gate = gp[off];
        const float hid  = hp_[off];
        const float z = sigmoidf_fast(gate);
        const float g = (hid >= 0.f) ? (hid + 0.5f) : sigmoidf_fast(hid);
        hcur = fmaf(1.f - z, hcur, z * g);
        const size_t o2 = (size_t)(t0 + j) * HD;
        op[o2] = hcur + ip[o2];
    }

    if (tc == 7) finals[b * HD + h] = hcur;   // pre-residual last h
}

// ---------------------------------------------------------------------------
// Launch: 4 layers of (GEMM -> scan). Ping-pong activations in device globals.
// Output layout: [ out (B,S,H) | finals (L,B,1,H) ]  (reference tuple order)
// ---------------------------------------------------------------------------
extern "C" void kernel_launch(void* const* d_in, const int* in_sizes, int n_in,
                              void* d_out, int out_size)
{
    const float* x  = (const float*)d_in[0];
    const float* h  = (const float*)d_in[1];   // (L,B,1,H)
    const float* W0 = (const float*)d_in[2];   // (2H,D)
    const float* b0 = (const float*)d_in[3];   // (2H,)
    const float* Wl = (const float*)d_in[4];   // (L-1,2H,H)
    const float* bl = (const float*)d_in[5];   // (L-1,2H)

    float* out    = (float*)d_out;
    float* finals = out + (size_t)MD * HD;

    float *gh, *bufA, *bufB;
    cudaGetSymbolAddress((void**)&gh,   g_gh);
    cudaGetSymbolAddress((void**)&bufA, g_bufA);
    cudaGetSymbolAddress((void**)&bufB, g_bufB);

    const dim3 ggrid(ED / 128, MD / 128);   // (16, 128)
    const dim3 sgrid(HD / 32, BD);          // (32, 8)

    const float* inp = x;
    for (int l = 0; l < LAYERS; l++) {
        const float* W  = (l == 0) ? W0 : Wl + (size_t)(l - 1) * ED * HD;
        const float* bb = (l == 0) ? b0 : bl + (size_t)(l - 1) * ED;
        float* o = (l == LAYERS - 1) ? out : ((l & 1) ? bufB : bufA);

        gemm_k<<<ggrid, 256>>>(inp, W, bb, gh);
        scan_k<<<sgrid, 256>>>(gh, inp, h + (size_t)l * BD * HD,
                               o, finals + (size_t)l * BD * HD);
        inp = o;
    }
}

// round 3
// speedup vs baseline: 2.4141x; 2.4141x over previous
#include <cuda_runtime.h>
#include <cuda_bf16.h>
#include <cstdint>

#define BD 8
#define SD 2048
#define DD 1024
#define HD 1024
#define ED 2048
#define MD (BD * SD)
#define LAYERS 4

// GEMM tiling
#define M_TILE 128
#define N_TILE 128
#define K_CHUNK 32
#define NCHUNK (DD / K_CHUNK)     // 32

// smem: 4 tiles (Ah, Al, Wh, Wl), each 128 rows x 32 bf16, row padded to 40 bf16 (80B)
#define ROW_B 80
#define TILE_B (128 * ROW_B)      // 10240
#define AH_OFF 0
#define AL_OFF (1 * TILE_B)
#define WH_OFF (2 * TILE_B)
#define WL_OFF (3 * TILE_B)
#define STAGE_B (4 * TILE_B)      // 40960
#define SMEM_TOTAL (2 * STAGE_B)  // 81920

// Scratch (allocation-free rule: device globals)
__device__ float         g_gh[(size_t)MD * ED];
__device__ float         g_o0[(size_t)MD * HD];
__device__ float         g_o1[(size_t)MD * HD];
__device__ __nv_bfloat16 g_xh[(size_t)MD * DD];
__device__ __nv_bfloat16 g_xl[(size_t)MD * DD];
__device__ __nv_bfloat16 g_wh[(size_t)LAYERS * ED * DD];
__device__ __nv_bfloat16 g_wl[(size_t)LAYERS * ED * DD];

__device__ __forceinline__ uint32_t smem_u32(const void* p) {
    uint32_t a;
    asm("{ .reg .u64 t; cvta.to.shared.u64 t, %1; cvt.u32.u64 %0, t; }"
        : "=r"(a) : "l"(p));
    return a;
}
__device__ __forceinline__ void cp16(uint32_t dst, const void* src) {
    asm volatile("cp.async.cg.shared.global [%0], [%1], 16;" :: "r"(dst), "l"(src));
}
__device__ __forceinline__ uint32_t lds32(uint32_t a) {
    uint32_t v;
    asm volatile("ld.shared.b32 %0, [%1];" : "=r"(v) : "r"(a));
    return v;
}
__device__ __forceinline__ void mma16816(float* c, uint32_t a0, uint32_t a1,
                                         uint32_t a2, uint32_t a3,
                                         uint32_t b0, uint32_t b1) {
    asm volatile(
        "mma.sync.aligned.m16n8k16.row.col.f32.bf16.bf16.f32 "
        "{%0,%1,%2,%3}, {%4,%5,%6,%7}, {%8,%9}, {%0,%1,%2,%3};"
        : "+f"(c[0]), "+f"(c[1]), "+f"(c[2]), "+f"(c[3])
        : "r"(a0), "r"(a1), "r"(a2), "r"(a3), "r"(b0), "r"(b1));
}

// ---------------------------------------------------------------------------
// GEMM: C[m,n] = sum_k A[m,k]*W[n,k] + bias[n]
// bf16 3-product error split into shared fp32 accumulators (HMMA path).
// ---------------------------------------------------------------------------
__global__ __launch_bounds__(256, 1) void gemm_mma(
    const __nv_bfloat16* __restrict__ Ah, const __nv_bfloat16* __restrict__ Al,
    const __nv_bfloat16* __restrict__ Wh, const __nv_bfloat16* __restrict__ Wl,
    const float* __restrict__ bias, float* __restrict__ C)
{
    extern __shared__ char smem[];
    const uint32_t sbase = smem_u32(smem);
    const int tid  = threadIdx.x;
    const int wid  = tid >> 5;
    const int lane = tid & 31;
    const int g    = lane >> 2;     // 0..7
    const int t4   = lane & 3;      // 0..3
    const int wm   = wid >> 1;      // 0..3  warp row  (32 rows)
    const int wn   = wid & 1;       // 0..1  warp col  (64 cols)
    const int bm   = blockIdx.y * M_TILE;
    const int bn   = blockIdx.x * N_TILE;

    float acc[2][8][4];
#pragma unroll
    for (int i = 0; i < 2; i++)
#pragma unroll
        for (int j = 0; j < 8; j++)
#pragma unroll
            for (int q = 0; q < 4; q++) acc[i][j][q] = 0.f;

    // async fill of one stage for k-chunk c
    auto fill = [&](int s, int c) {
        const uint32_t st = sbase + s * STAGE_B;
        const int k0 = c * K_CHUNK;
#pragma unroll
        for (int rep = 0; rep < 2; rep++) {
            const int v  = tid + rep * 256;     // 0..511
            const int r  = v >> 2;              // 0..127
            const int c4 = v & 3;               // 16B chunk in row
            const uint32_t d = r * ROW_B + c4 * 16;
            const size_t ga = (size_t)(bm + r) * DD + k0 + c4 * 8;
            const size_t gw = (size_t)(bn + r) * DD + k0 + c4 * 8;
            cp16(st + AH_OFF + d, Ah + ga);
            cp16(st + AL_OFF + d, Al + ga);
            cp16(st + WH_OFF + d, Wh + gw);
            cp16(st + WL_OFF + d, Wl + gw);
        }
        asm volatile("cp.async.commit_group;" ::: "memory");
    };

    fill(0, 0);

#pragma unroll 1
    for (int c = 0; c < NCHUNK; c++) {
        const int s = c & 1;
        if (c + 1 < NCHUNK) {
            fill(s ^ 1, c + 1);
            asm volatile("cp.async.wait_group 1;" ::: "memory");
        } else {
            asm volatile("cp.async.wait_group 0;" ::: "memory");
        }
        __syncthreads();

        const uint32_t st = sbase + s * STAGE_B;
#pragma unroll
        for (int k16 = 0; k16 < 2; k16++) {
            const uint32_t kb = k16 * 32 + t4 * 4;   // byte offset of 2 bf16 at col 2t
            uint32_t ah[2][4], al[2][4], wh[8][2], wl[8][2];
#pragma unroll
            for (int i = 0; i < 2; i++) {
                const uint32_t rb = (uint32_t)(wm * 32 + i * 16 + g) * ROW_B + kb;
                ah[i][0] = lds32(st + AH_OFF + rb);
                ah[i][1] = lds32(st + AH_OFF + rb + 8 * ROW_B);
                ah[i][2] = lds32(st + AH_OFF + rb + 16);
                ah[i][3] = lds32(st + AH_OFF + rb + 8 * ROW_B + 16);
                al[i][0] = lds32(st + AL_OFF + rb);
                al[i][1] = lds32(st + AL_OFF + rb + 8 * ROW_B);
                al[i][2] = lds32(st + AL_OFF + rb + 16);
                al[i][3] = lds32(st + AL_OFF + rb + 8 * ROW_B + 16);
            }
#pragma unroll
            for (int j = 0; j < 8; j++) {
                const uint32_t rb = (uint32_t)(wn * 64 + j * 8 + g) * ROW_B + kb;
                wh[j][0] = lds32(st + WH_OFF + rb);
                wh[j][1] = lds32(st + WH_OFF + rb + 16);
                wl[j][0] = lds32(st + WL_OFF + rb);
                wl[j][1] = lds32(st + WL_OFF + rb + 16);
            }
#pragma unroll
            for (int i = 0; i < 2; i++)
#pragma unroll
                for (int j = 0; j < 8; j++) {
                    mma16816(acc[i][j], ah[i][0], ah[i][1], ah[i][2], ah[i][3],
                             wh[j][0], wh[j][1]);
                    mma16816(acc[i][j], ah[i][0], ah[i][1], ah[i][2], ah[i][3],
                             wl[j][0], wl[j][1]);
                    mma16816(acc[i][j], al[i][0], al[i][1], al[i][2], al[i][3],
                             wh[j][0], wh[j][1]);
                }
        }
        __syncthreads();
    }

    // epilogue: add bias, float2 stores
#pragma unroll
    for (int i = 0; i < 2; i++) {
        const int r0 = bm + wm * 32 + i * 16 + g;
#pragma unroll
        for (int j = 0; j < 8; j++) {
            const int col = bn + wn * 64 + j * 8 + 2 * t4;
            const float b0 = bias[col], b1 = bias[col + 1];
            float2 v0 = { acc[i][j][0] + b0, acc[i][j][1] + b1 };
            float2 v1 = { acc[i][j][2] + b0, acc[i][j][3] + b1 };
            *(float2*)(C + (size_t)r0 * ED + col)       = v0;
            *(float2*)(C + (size_t)(r0 + 8) * ED + col) = v1;
        }
    }
}

// ---------------------------------------------------------------------------
// conversions: fp32 -> bf16 hi/lo
// ---------------------------------------------------------------------------
__global__ __launch_bounds__(256) void conv_split(
    const float* __restrict__ src, __nv_bfloat16* __restrict__ hi,
    __nv_bfloat16* __restrict__ lo, size_t n)
{
    for (size_t i = (size_t)blockIdx.x * blockDim.x + threadIdx.x; i < n;
         i += (size_t)gridDim.x * blockDim.x) {
        float x = src[i];
        __nv_bfloat16 h = __float2bfloat16(x);
        hi[i] = h;
        lo[i] = __float2bfloat16(x - __bfloat162float(h));
    }
}

__global__ __launch_bounds__(256) void conv_w(
    const float* __restrict__ W0, const float* __restrict__ Wl,
    __nv_bfloat16* __restrict__ hi, __nv_bfloat16* __restrict__ lo)
{
    const size_t per = (size_t)ED * DD;
    const size_t n = (size_t)LAYERS * per;
    for (size_t i = (size_t)blockIdx.x * blockDim.x + threadIdx.x; i < n;
         i += (size_t)gridDim.x * blockDim.x) {
        float x = (i < per) ? W0[i] : Wl[i - per];
        __nv_bfloat16 h = __float2bfloat16(x);
        hi[i] = h;
        lo[i] = __float2bfloat16(x - __bfloat162float(h));
    }
}

// ---------------------------------------------------------------------------
// Scan + residual + fused bf16 split of next-layer input
// ---------------------------------------------------------------------------
__device__ __forceinline__ float sigf(float x) { return 1.f / (1.f + __expf(-x)); }

__global__ __launch_bounds__(1024) void scan_split_k(
    const float* __restrict__ gh, const float* __restrict__ inp,
    const float* __restrict__ h0, float* __restrict__ outp,
    __nv_bfloat16* __restrict__ outh, __nv_bfloat16* __restrict__ outl,
    float* __restrict__ finals, int do_split)
{
    const int b  = blockIdx.y;
    const int hx = threadIdx.x & 31;
    const int tc = threadIdx.x >> 5;
    const int h  = blockIdx.x * 32 + hx;
    const int CH = SD / 32;
    const int t0 = tc * CH;

    const size_t rowbase = (size_t)b * SD;
    const float* gp = gh + rowbase * ED + h;
    const float* hp = gp + HD;

    float Ac = 1.f, Cc = 0.f;
#pragma unroll 4
    for (int j = 0; j < CH; j++) {
        const size_t off = (size_t)(t0 + j) * ED;
        const float z = sigf(gp[off]);
        const float hid = hp[off];
        const float gg = (hid >= 0.f) ? (hid + 0.5f) : sigf(hid);
        const float a = 1.f - z;
        Cc = fmaf(a, Cc, z * gg);
        Ac *= a;
    }

    __shared__ float sA[32][33], sC[32][33];
    sA[tc][hx] = Ac; sC[tc][hx] = Cc;
    __syncthreads();

    const float hprev = h0[b * HD + h];
    float hcur = (hprev >= 0.f) ? (hprev + 0.5f) : sigf(hprev);
    for (int c = 0; c < tc; c++) hcur = fmaf(sA[c][hx], hcur, sC[c][hx]);

    const size_t obase = rowbase * HD + h;
    const float* ip = inp + obase;
    float* op = outp + obase;
#pragma unroll 4
    for (int j = 0; j < CH; j++) {
        const size_t off = (size_t)(t0 + j) * ED;
        const float z = sigf(gp[off]);
        const float hid = hp[off];
        const float gg = (hid >= 0.f) ? (hid + 0.5f) : sigf(hid);
        hcur = fmaf(1.f - z, hcur, z * gg);
        const size_t o2 = (size_t)(t0 + j) * HD;
        const float o = hcur + ip[o2];
        op[o2] = o;
        if (do_split) {
            __nv_bfloat16 oh = __float2bfloat16(o);
            outh[obase + o2] = oh;
            outl[obase + o2] = __float2bfloat16(o - __bfloat162float(oh));
        }
    }
    if (tc == 31) finals[b * HD + h] = hcur;
}

// ---------------------------------------------------------------------------
extern "C" void kernel_launch(void* const* d_in, const int* in_sizes, int n_in,
                              void* d_out, int out_size)
{
    const float* x  = (const float*)d_in[0];
    const float* h  = (const float*)d_in[1];
    const float* W0 = (const float*)d_in[2];
    const float* b0 = (const float*)d_in[3];
    const float* Wl = (const float*)d_in[4];
    const float* bl = (const float*)d_in[5];

    float* out    = (float*)d_out;
    float* finals = out + (size_t)MD * HD;

    float *gh, *o0, *o1;
    __nv_bfloat16 *xh, *xl, *wh, *wl;
    cudaGetSymbolAddress((void**)&gh, g_gh);
    cudaGetSymbolAddress((void**)&o0, g_o0);
    cudaGetSymbolAddress((void**)&o1, g_o1);
    cudaGetSymbolAddress((void**)&xh, g_xh);
    cudaGetSymbolAddress((void**)&xl, g_xl);
    cudaGetSymbolAddress((void**)&wh, g_wh);
    cudaGetSymbolAddress((void**)&wl, g_wl);

    cudaFuncSetAttribute(gemm_mma, cudaFuncAttributeMaxDynamicSharedMemorySize,
                         SMEM_TOTAL);

    conv_w<<<512, 256>>>(W0, Wl, wh, wl);
    conv_split<<<1024, 256>>>(x, xh, xl, (size_t)MD * DD);

    const dim3 ggrid(ED / N_TILE, MD / M_TILE);   // (16, 128)
    const dim3 sgrid(HD / 32, BD);                // (32, 8)

    const float* inp = x;
    for (int l = 0; l < LAYERS; l++) {
        const size_t woff = (size_t)l * ED * DD;
        const float* bb = (l == 0) ? b0 : bl + (size_t)(l - 1) * ED;
        float* o = (l == LAYERS - 1) ? out : ((l & 1) ? o1 : o0);
        const int do_split = (l < LAYERS - 1);

        gemm_mma<<<ggrid, 256, SMEM_TOTAL>>>(xh, xl, wh + woff, wl + woff, bb, gh);
        scan_split_k<<<sgrid, 1024>>>(gh, inp, h + (size_t)l * BD * HD, o,
                                      xh, xl, finals + (size_t)l * BD * HD, do_split);
        inp = o;
    }
}

// round 4
// speedup vs baseline: 2.4537x; 1.0164x over previous
#include <cuda_runtime.h>
#include <cuda_bf16.h>
#include <cstdint>

#define BD 8
#define SD 2048
#define DD 1024
#define HD 1024
#define ED 2048
#define MD (BD * SD)
#define LAYERS 4

#define M_TILE 128
#define N_TILE 128
#define K_CHUNK 32
#define NCHUNK (DD / K_CHUNK)     // 32

#define ROW_B 80                  // 32 bf16 + 16B pad -> conflict-free LDSM
#define TILE_B (128 * ROW_B)
#define AH_OFF 0
#define AL_OFF (1 * TILE_B)
#define WH_OFF (2 * TILE_B)
#define WL_OFF (3 * TILE_B)
#define STAGE_B (4 * TILE_B)      // 40960
#define SMEM_TOTAL (2 * STAGE_B)  // 81920

__device__ float         g_gh[(size_t)MD * ED];
__device__ float         g_o0[(size_t)MD * HD];
__device__ float         g_o1[(size_t)MD * HD];
__device__ __nv_bfloat16 g_xh[(size_t)MD * DD];
__device__ __nv_bfloat16 g_xl[(size_t)MD * DD];
__device__ __nv_bfloat16 g_wh[(size_t)LAYERS * ED * DD];
__device__ __nv_bfloat16 g_wl[(size_t)LAYERS * ED * DD];

__device__ __forceinline__ uint32_t smem_u32(const void* p) {
    uint32_t a;
    asm("{ .reg .u64 t; cvta.to.shared.u64 t, %1; cvt.u32.u64 %0, t; }"
        : "=r"(a) : "l"(p));
    return a;
}
__device__ __forceinline__ void cp16(uint32_t dst, const void* src) {
    asm volatile("cp.async.cg.shared.global [%0], [%1], 16;" :: "r"(dst), "l"(src));
}
__device__ __forceinline__ void ldsm4(uint32_t* r, uint32_t addr) {
    asm volatile("ldmatrix.sync.aligned.m8n8.x4.shared.b16 {%0,%1,%2,%3}, [%4];"
                 : "=r"(r[0]), "=r"(r[1]), "=r"(r[2]), "=r"(r[3]) : "r"(addr));
}
__device__ __forceinline__ void mma16816(float* c, const uint32_t* a,
                                         uint32_t b0, uint32_t b1) {
    asm volatile(
        "mma.sync.aligned.m16n8k16.row.col.f32.bf16.bf16.f32 "
        "{%0,%1,%2,%3}, {%4,%5,%6,%7}, {%8,%9}, {%0,%1,%2,%3};"
        : "+f"(c[0]), "+f"(c[1]), "+f"(c[2]), "+f"(c[3])
        : "r"(a[0]), "r"(a[1]), "r"(a[2]), "r"(a[3]), "r"(b0), "r"(b1));
}

// ---------------------------------------------------------------------------
// GEMM: C[m,n] = sum_k A[m,k]*W[n,k] + bias[n] (bf16 3-product error split)
// ---------------------------------------------------------------------------
__global__ __launch_bounds__(256, 1) void gemm_mma(
    const __nv_bfloat16* __restrict__ Ah, const __nv_bfloat16* __restrict__ Al,
    const __nv_bfloat16* __restrict__ Wh, const __nv_bfloat16* __restrict__ Wl,
    const float* __restrict__ bias, float* __restrict__ C)
{
    extern __shared__ char smem[];
    const uint32_t sbase = smem_u32(smem);
    const int tid  = threadIdx.x;
    const int wid  = tid >> 5;
    const int lane = tid & 31;
    const int g    = lane >> 2;
    const int t4   = lane & 3;
    const int wm   = wid >> 1;      // warp row (32 m-rows)
    const int wn   = wid & 1;       // warp col (64 n-cols)
    const int bm   = blockIdx.y * M_TILE;
    const int bn   = blockIdx.x * N_TILE;

    float acc[2][8][4];
#pragma unroll
    for (int i = 0; i < 2; i++)
#pragma unroll
        for (int j = 0; j < 8; j++)
#pragma unroll
            for (int q = 0; q < 4; q++) acc[i][j][q] = 0.f;

    auto fill = [&](int s, int c) {
        const uint32_t st = sbase + s * STAGE_B;
        const int k0 = c * K_CHUNK;
#pragma unroll
        for (int rep = 0; rep < 2; rep++) {
            const int v  = tid + rep * 256;
            const int r  = v >> 2;
            const int c4 = v & 3;
            const uint32_t d = r * ROW_B + c4 * 16;
            const size_t ga = (size_t)(bm + r) * DD + k0 + c4 * 8;
            const size_t gw = (size_t)(bn + r) * DD + k0 + c4 * 8;
            cp16(st + AH_OFF + d, Ah + ga);
            cp16(st + AL_OFF + d, Al + ga);
            cp16(st + WH_OFF + d, Wh + gw);
            cp16(st + WL_OFF + d, Wl + gw);
        }
        asm volatile("cp.async.commit_group;" ::: "memory");
    };

    // LDSM address offsets (within a stage, per k16 added later)
    // A: lanes 0-15 -> m-row (lane&15) at k-half 0; lanes 16-31 -> k-half 1
    const uint32_t a_row = (uint32_t)(wm * 32 + (lane & 15));
    const uint32_t a_off = a_row * ROW_B + ((lane >> 4) & 1) * 16;
    // W: matrix idx = lane>>3; row = jp*16 + (mi>>1)*8 + (lane&7); k-half = mi&1
    const uint32_t w_mi  = (uint32_t)(lane >> 3);
    const uint32_t w_row0 = (uint32_t)(wn * 64 + (w_mi >> 1) * 8 + (lane & 7));
    const uint32_t w_off = w_row0 * ROW_B + (w_mi & 1) * 16;

    fill(0, 0);

#pragma unroll 1
    for (int c = 0; c < NCHUNK; c++) {
        const int s = c & 1;
        if (c + 1 < NCHUNK) {
            fill(s ^ 1, c + 1);
            asm volatile("cp.async.wait_group 1;" ::: "memory");
        } else {
            asm volatile("cp.async.wait_group 0;" ::: "memory");
        }
        __syncthreads();

        const uint32_t st = sbase + s * STAGE_B;
#pragma unroll
        for (int k16 = 0; k16 < 2; k16++) {
            const uint32_t kb = (uint32_t)k16 * 32;
            uint32_t ah[2][4], al[2][4], wh[4][4], wl[4][4];
#pragma unroll
            for (int i = 0; i < 2; i++) {
                ldsm4(ah[i], st + AH_OFF + a_off + i * (16 * ROW_B) + kb);
                ldsm4(al[i], st + AL_OFF + a_off + i * (16 * ROW_B) + kb);
            }
#pragma unroll
            for (int jp = 0; jp < 4; jp++) {
                ldsm4(wh[jp], st + WH_OFF + w_off + jp * (16 * ROW_B) + kb);
                ldsm4(wl[jp], st + WL_OFF + w_off + jp * (16 * ROW_B) + kb);
            }
#pragma unroll
            for (int i = 0; i < 2; i++)
#pragma unroll
                for (int jp = 0; jp < 4; jp++) {
                    mma16816(acc[i][jp * 2],     ah[i], wh[jp][0], wh[jp][1]);
                    mma16816(acc[i][jp * 2 + 1], ah[i], wh[jp][2], wh[jp][3]);
                    mma16816(acc[i][jp * 2],     ah[i], wl[jp][0], wl[jp][1]);
                    mma16816(acc[i][jp * 2 + 1], ah[i], wl[jp][2], wl[jp][3]);
                    mma16816(acc[i][jp * 2],     al[i], wh[jp][0], wh[jp][1]);
                    mma16816(acc[i][jp * 2 + 1], al[i], wh[jp][2], wh[jp][3]);
                }
        }
        __syncthreads();
    }

#pragma unroll
    for (int i = 0; i < 2; i++) {
        const int r0 = bm + wm * 32 + i * 16 + g;
#pragma unroll
        for (int j = 0; j < 8; j++) {
            const int col = bn + wn * 64 + j * 8 + 2 * t4;
            const float b0 = bias[col], b1 = bias[col + 1];
            float2 v0 = { acc[i][j][0] + b0, acc[i][j][1] + b1 };
            float2 v1 = { acc[i][j][2] + b0, acc[i][j][3] + b1 };
            *(float2*)(C + (size_t)r0 * ED + col)       = v0;
            *(float2*)(C + (size_t)(r0 + 8) * ED + col) = v1;
        }
    }
}

// ---------------------------------------------------------------------------
__global__ __launch_bounds__(256) void conv_split(
    const float* __restrict__ src, __nv_bfloat16* __restrict__ hi,
    __nv_bfloat16* __restrict__ lo, size_t n)
{
    for (size_t i = (size_t)blockIdx.x * blockDim.x + threadIdx.x; i < n;
         i += (size_t)gridDim.x * blockDim.x) {
        float x = src[i];
        __nv_bfloat16 h = __float2bfloat16(x);
        hi[i] = h;
        lo[i] = __float2bfloat16(x - __bfloat162float(h));
    }
}

__global__ __launch_bounds__(256) void conv_w(
    const float* __restrict__ W0, const float* __restrict__ Wl,
    __nv_bfloat16* __restrict__ hi, __nv_bfloat16* __restrict__ lo)
{
    const size_t per = (size_t)ED * DD;
    const size_t n = (size_t)LAYERS * per;
    for (size_t i = (size_t)blockIdx.x * blockDim.x + threadIdx.x; i < n;
         i += (size_t)gridDim.x * blockDim.x) {
        float x = (i < per) ? W0[i] : Wl[i - per];
        __nv_bfloat16 h = __float2bfloat16(x);
        hi[i] = h;
        lo[i] = __float2bfloat16(x - __bfloat162float(h));
    }
}

// ---------------------------------------------------------------------------
__device__ __forceinline__ float sigf(float x) { return 1.f / (1.f + __expf(-x)); }

__global__ __launch_bounds__(1024) void scan_split_k(
    const float* __restrict__ gh, const float* __restrict__ inp,
    const float* __restrict__ h0, float* __restrict__ outp,
    __nv_bfloat16* __restrict__ outh, __nv_bfloat16* __restrict__ outl,
    float* __restrict__ finals, int do_split)
{
    const int b  = blockIdx.y;
    const int hx = threadIdx.x & 31;
    const int tc = threadIdx.x >> 5;
    const int h  = blockIdx.x * 32 + hx;
    const int CH = SD / 32;
    const int t0 = tc * CH;

    const size_t rowbase = (size_t)b * SD;
    const float* gp = gh + rowbase * ED + h;
    const float* hp = gp + HD;

    float Ac = 1.f, Cc = 0.f;
#pragma unroll 4
    for (int j = 0; j < CH; j++) {
        const size_t off = (size_t)(t0 + j) * ED;
        const float z = sigf(gp[off]);
        const float hid = hp[off];
        const float gg = (hid >= 0.f) ? (hid + 0.5f) : sigf(hid);
        const float a = 1.f - z;
        Cc = fmaf(a, Cc, z * gg);
        Ac *= a;
    }

    __shared__ float sA[32][33], sC[32][33];
    sA[tc][hx] = Ac; sC[tc][hx] = Cc;
    __syncthreads();

    const float hprev = h0[b * HD + h];
    float hcur = (hprev >= 0.f) ? (hprev + 0.5f) : sigf(hprev);
    for (int c = 0; c < tc; c++) hcur = fmaf(sA[c][hx], hcur, sC[c][hx]);

    const size_t obase = rowbase * HD + h;
    const float* ip = inp + obase;
    float* op = outp + obase;
#pragma unroll 4
    for (int j = 0; j < CH; j++) {
        const size_t off = (size_t)(t0 + j) * ED;
        const float z = sigf(gp[off]);
        const float hid = hp[off];
        const float gg = (hid >= 0.f) ? (hid + 0.5f) : sigf(hid);
        hcur = fmaf(1.f - z, hcur, z * gg);
        const size_t o2 = (size_t)(t0 + j) * HD;
        const float o = hcur + ip[o2];
        op[o2] = o;
        if (do_split) {
            __nv_bfloat16 oh = __float2bfloat16(o);
            outh[obase + o2] = oh;
            outl[obase + o2] = __float2bfloat16(o - __bfloat162float(oh));
        }
    }
    if (tc == 31) finals[b * HD + h] = hcur;
}

// ---------------------------------------------------------------------------
extern "C" void kernel_launch(void* const* d_in, const int* in_sizes, int n_in,
                              void* d_out, int out_size)
{
    const float* x  = (const float*)d_in[0];
    const float* h  = (const float*)d_in[1];
    const float* W0 = (const float*)d_in[2];
    const float* b0 = (const float*)d_in[3];
    const float* Wl = (const float*)d_in[4];
    const float* bl = (const float*)d_in[5];

    float* out    = (float*)d_out;
    float* finals = out + (size_t)MD * HD;

    float *gh, *o0, *o1;
    __nv_bfloat16 *xh, *xl, *wh, *wl;
    cudaGetSymbolAddress((void**)&gh, g_gh);
    cudaGetSymbolAddress((void**)&o0, g_o0);
    cudaGetSymbolAddress((void**)&o1, g_o1);
    cudaGetSymbolAddress((void**)&xh, g_xh);
    cudaGetSymbolAddress((void**)&xl, g_xl);
    cudaGetSymbolAddress((void**)&wh, g_wh);
    cudaGetSymbolAddress((void**)&wl, g_wl);

    cudaFuncSetAttribute(gemm_mma, cudaFuncAttributeMaxDynamicSharedMemorySize,
                         SMEM_TOTAL);

    conv_w<<<512, 256>>>(W0, Wl, wh, wl);
    conv_split<<<1024, 256>>>(x, xh, xl, (size_t)MD * DD);

    const dim3 ggrid(ED / N_TILE, MD / M_TILE);   // (16, 128)
    const dim3 sgrid(HD / 32, BD);                // (32, 8)

    const float* inp = x;
    for (int l = 0; l < LAYERS; l++) {
        const size_t woff = (size_t)l * ED * DD;
        const float* bb = (l == 0) ? b0 : bl + (size_t)(l - 1) * ED;
        float* o = (l == LAYERS - 1) ? out : ((l & 1) ? o1 : o0);
        const int do_split = (l < LAYERS - 1);

        gemm_mma<<<ggrid, 256, SMEM_TOTAL>>>(xh, xl, wh + woff, wl + woff, bb, gh);
        scan_split_k<<<sgrid, 1024>>>(gh, inp, h + (size_t)l * BD * HD, o,
                                      xh, xl, finals + (size_t)l * BD * HD, do_split);
        inp = o;
    }
}

// round 5
// speedup vs baseline: 2.7910x; 1.1375x over previous
#include <cuda_runtime.h>
#include <cuda_bf16.h>
#include <cstdint>

#define BD 8
#define SD 2048
#define DD 1024
#define HD 1024
#define ED 2048
#define MD (BD * SD)
#define LAYERS 4

#define M_TILE 128
#define N_TILE 256
#define K_CHUNK 32
#define NCHUNK (DD / K_CHUNK)     // 32

#define ROW_B 80                  // 64B data + 16B pad: conflict-free LDSM
#define A_TILE_B (128 * ROW_B)    // 10240
#define W_TILE_B (256 * ROW_B)    // 20480
#define AH_OFF 0
#define AL_OFF A_TILE_B
#define WH_OFF (2 * A_TILE_B)
#define WL_OFF (2 * A_TILE_B + W_TILE_B)
#define STAGE_B (2 * A_TILE_B + 2 * W_TILE_B)   // 61440
#define NSTAGE 3
#define SMEM_TOTAL (NSTAGE * STAGE_B)           // 184320

__device__ float         g_gh[(size_t)MD * ED];
__device__ float         g_o0[(size_t)MD * HD];
__device__ float         g_o1[(size_t)MD * HD];
__device__ __nv_bfloat16 g_xh[(size_t)MD * DD];
__device__ __nv_bfloat16 g_xl[(size_t)MD * DD];
__device__ __nv_bfloat16 g_wh[(size_t)LAYERS * ED * DD];
__device__ __nv_bfloat16 g_wl[(size_t)LAYERS * ED * DD];

__device__ __forceinline__ uint32_t smem_u32(const void* p) {
    uint32_t a;
    asm("{ .reg .u64 t; cvta.to.shared.u64 t, %1; cvt.u32.u64 %0, t; }"
        : "=r"(a) : "l"(p));
    return a;
}
__device__ __forceinline__ void cp16(uint32_t dst, const void* src) {
    asm volatile("cp.async.cg.shared.global [%0], [%1], 16;" :: "r"(dst), "l"(src));
}
__device__ __forceinline__ void ldsm4(uint32_t* r, uint32_t addr) {
    asm volatile("ldmatrix.sync.aligned.m8n8.x4.shared.b16 {%0,%1,%2,%3}, [%4];"
                 : "=r"(r[0]), "=r"(r[1]), "=r"(r[2]), "=r"(r[3]) : "r"(addr));
}
__device__ __forceinline__ void mma16816(float* c, const uint32_t* a,
                                         uint32_t b0, uint32_t b1) {
    asm volatile(
        "mma.sync.aligned.m16n8k16.row.col.f32.bf16.bf16.f32 "
        "{%0,%1,%2,%3}, {%4,%5,%6,%7}, {%8,%9}, {%0,%1,%2,%3};"
        : "+f"(c[0]), "+f"(c[1]), "+f"(c[2]), "+f"(c[3])
        : "r"(a[0]), "r"(a[1]), "r"(a[2]), "r"(a[3]), "r"(b0), "r"(b1));
}

// ---------------------------------------------------------------------------
// GEMM: C[m,n] = sum_k A[m,k]*W[n,k] + bias[n] (bf16 3-product error split)
// CTA 128x256, 8 warps (2 wm x 4 wn), warp tile 64x64, 3-stage cp.async ring.
// ---------------------------------------------------------------------------
__global__ __launch_bounds__(256, 1) void gemm_mma(
    const __nv_bfloat16* __restrict__ Ah, const __nv_bfloat16* __restrict__ Al,
    const __nv_bfloat16* __restrict__ Wh, const __nv_bfloat16* __restrict__ Wl,
    const float* __restrict__ bias, float* __restrict__ C)
{
    extern __shared__ char smem[];
    const uint32_t sbase = smem_u32(smem);
    const int tid  = threadIdx.x;
    const int wid  = tid >> 5;
    const int lane = tid & 31;
    const int g    = lane >> 2;
    const int t4   = lane & 3;
    const int wm   = wid >> 2;        // 0..1 : 64 m-rows
    const int wn   = wid & 3;         // 0..3 : 64 n-cols
    const int bm   = blockIdx.y * M_TILE;
    const int bn   = blockIdx.x * N_TILE;

    float acc[4][8][4];               // [m16 tile][n8 tile][quad]
#pragma unroll
    for (int i = 0; i < 4; i++)
#pragma unroll
        for (int j = 0; j < 8; j++)
#pragma unroll
            for (int q = 0; q < 4; q++) acc[i][j][q] = 0.f;

    auto fill = [&](int s, int c) {
        const uint32_t st = sbase + s * STAGE_B;
        const int k0 = c * K_CHUNK;
        // A tiles: 128 rows x 4 16B-chunks x {hi,lo} -> 2 reps of 256
#pragma unroll
        for (int rep = 0; rep < 2; rep++) {
            const int v  = tid + rep * 256;
            const int r  = v >> 2, c4 = v & 3;
            const uint32_t d = r * ROW_B + c4 * 16;
            const size_t ga = (size_t)(bm + r) * DD + k0 + c4 * 8;
            cp16(st + AH_OFF + d, Ah + ga);
            cp16(st + AL_OFF + d, Al + ga);
        }
        // W tiles: 256 rows x 4 chunks x {hi,lo} -> 4 reps of 256
#pragma unroll
        for (int rep = 0; rep < 4; rep++) {
            const int v  = tid + rep * 256;
            const int r  = v >> 2, c4 = v & 3;
            const uint32_t d = r * ROW_B + c4 * 16;
            const size_t gw = (size_t)(bn + r) * DD + k0 + c4 * 8;
            cp16(st + WH_OFF + d, Wh + gw);
            cp16(st + WL_OFF + d, Wl + gw);
        }
        asm volatile("cp.async.commit_group;" ::: "memory");
    };

    // LDSM address templates (k16 byte offset added later)
    // A: matrix rows a_row..+15, k-half by lane>>4
    const uint32_t a_off = (uint32_t)(wm * 64 + (lane & 15)) * ROW_B
                         + ((lane >> 4) & 1) * 16;
    // W: mi = lane>>3 selects (row-octet, k-half)
    const uint32_t w_mi  = (uint32_t)(lane >> 3);
    const uint32_t w_off = (uint32_t)(wn * 64 + (w_mi >> 1) * 8 + (lane & 7)) * ROW_B
                         + (w_mi & 1) * 16;

    fill(0, 0);
    fill(1, 1);

#pragma unroll 1
    for (int c = 0; c < NCHUNK; c++) {
        if (c + 1 < NCHUNK)
            asm volatile("cp.async.wait_group 1;" ::: "memory");
        else
            asm volatile("cp.async.wait_group 0;" ::: "memory");
        __syncthreads();

        if (c + 2 < NCHUNK) fill((c + 2) % NSTAGE, c + 2);

        const uint32_t st = sbase + (c % NSTAGE) * STAGE_B;
#pragma unroll
        for (int k16 = 0; k16 < 2; k16++) {
            const uint32_t kb = (uint32_t)k16 * 32;
            uint32_t whf[4][4], wlf[4][4];
#pragma unroll
            for (int jp = 0; jp < 4; jp++) {
                ldsm4(whf[jp], st + WH_OFF + w_off + jp * (16 * ROW_B) + kb);
                ldsm4(wlf[jp], st + WL_OFF + w_off + jp * (16 * ROW_B) + kb);
            }
#pragma unroll
            for (int mi = 0; mi < 4; mi++) {
                uint32_t ahf[4], alf[4];
                ldsm4(ahf, st + AH_OFF + a_off + mi * (16 * ROW_B) + kb);
                ldsm4(alf, st + AL_OFF + a_off + mi * (16 * ROW_B) + kb);
#pragma unroll
                for (int jp = 0; jp < 4; jp++) {
                    mma16816(acc[mi][jp * 2],     ahf, whf[jp][0], whf[jp][1]);
                    mma16816(acc[mi][jp * 2 + 1], ahf, whf[jp][2], whf[jp][3]);
                    mma16816(acc[mi][jp * 2],     ahf, wlf[jp][0], wlf[jp][1]);
                    mma16816(acc[mi][jp * 2 + 1], ahf, wlf[jp][2], wlf[jp][3]);
                    mma16816(acc[mi][jp * 2],     alf, whf[jp][0], whf[jp][1]);
                    mma16816(acc[mi][jp * 2 + 1], alf, whf[jp][2], whf[jp][3]);
                }
            }
        }
    }

    // epilogue: bias + float2 stores
    float bj[8][2];
#pragma unroll
    for (int j = 0; j < 8; j++) {
        const int col = bn + wn * 64 + j * 8 + 2 * t4;
        bj[j][0] = bias[col]; bj[j][1] = bias[col + 1];
    }
#pragma unroll
    for (int mi = 0; mi < 4; mi++) {
        const int r0 = bm + wm * 64 + mi * 16 + g;
#pragma unroll
        for (int j = 0; j < 8; j++) {
            const int col = bn + wn * 64 + j * 8 + 2 * t4;
            float2 v0 = { acc[mi][j][0] + bj[j][0], acc[mi][j][1] + bj[j][1] };
            float2 v1 = { acc[mi][j][2] + bj[j][0], acc[mi][j][3] + bj[j][1] };
            *(float2*)(C + (size_t)r0 * ED + col)       = v0;
            *(float2*)(C + (size_t)(r0 + 8) * ED + col) = v1;
        }
    }
}

// ---------------------------------------------------------------------------
__global__ __launch_bounds__(256) void conv_split(
    const float* __restrict__ src, __nv_bfloat16* __restrict__ hi,
    __nv_bfloat16* __restrict__ lo, size_t n)
{
    for (size_t i = (size_t)blockIdx.x * blockDim.x + threadIdx.x; i < n;
         i += (size_t)gridDim.x * blockDim.x) {
        float x = src[i];
        __nv_bfloat16 h = __float2bfloat16(x);
        hi[i] = h;
        lo[i] = __float2bfloat16(x - __bfloat162float(h));
    }
}

__global__ __launch_bounds__(256) void conv_w(
    const float* __restrict__ W0, const float* __restrict__ Wl,
    __nv_bfloat16* __restrict__ hi, __nv_bfloat16* __restrict__ lo)
{
    const size_t per = (size_t)ED * DD;
    const size_t n = (size_t)LAYERS * per;
    for (size_t i = (size_t)blockIdx.x * blockDim.x + threadIdx.x; i < n;
         i += (size_t)gridDim.x * blockDim.x) {
        float x = (i < per) ? W0[i] : Wl[i - per];
        __nv_bfloat16 h = __float2bfloat16(x);
        hi[i] = h;
        lo[i] = __float2bfloat16(x - __bfloat162float(h));
    }
}

// ---------------------------------------------------------------------------
__device__ __forceinline__ float sigf(float x) { return 1.f / (1.f + __expf(-x)); }

__global__ __launch_bounds__(1024) void scan_split_k(
    const float* __restrict__ gh, const float* __restrict__ inp,
    const float* __restrict__ h0, float* __restrict__ outp,
    __nv_bfloat16* __restrict__ outh, __nv_bfloat16* __restrict__ outl,
    float* __restrict__ finals, int do_split)
{
    const int b  = blockIdx.y;
    const int hx = threadIdx.x & 31;
    const int tc = threadIdx.x >> 5;
    const int h  = blockIdx.x * 32 + hx;
    const int CH = SD / 32;
    const int t0 = tc * CH;

    const size_t rowbase = (size_t)b * SD;
    const float* gp = gh + rowbase * ED + h;
    const float* hp = gp + HD;

    float Ac = 1.f, Cc = 0.f;
#pragma unroll 4
    for (int j = 0; j < CH; j++) {
        const size_t off = (size_t)(t0 + j) * ED;
        const float z = sigf(gp[off]);
        const float hid = hp[off];
        const float gg = (hid >= 0.f) ? (hid + 0.5f) : sigf(hid);
        const float a = 1.f - z;
        Cc = fmaf(a, Cc, z * gg);
        Ac *= a;
    }

    __shared__ float sA[32][33], sC[32][33];
    sA[tc][hx] = Ac; sC[tc][hx] = Cc;
    __syncthreads();

    const float hprev = h0[b * HD + h];
    float hcur = (hprev >= 0.f) ? (hprev + 0.5f) : sigf(hprev);
    for (int c = 0; c < tc; c++) hcur = fmaf(sA[c][hx], hcur, sC[c][hx]);

    const size_t obase = rowbase * HD + h;
    const float* ip = inp + obase;
    float* op = outp + obase;
#pragma unroll 4
    for (int j = 0; j < CH; j++) {
        const size_t off = (size_t)(t0 + j) * ED;
        const float z = sigf(gp[off]);
        const float hid = hp[off];
        const float gg = (hid >= 0.f) ? (hid + 0.5f) : sigf(hid);
        hcur = fmaf(1.f - z, hcur, z * gg);
        const size_t o2 = (size_t)(t0 + j) * HD;
        const float o = hcur + ip[o2];
        op[o2] = o;
        if (do_split) {
            __nv_bfloat16 oh = __float2bfloat16(o);
            outh[obase + o2] = oh;
            outl[obase + o2] = __float2bfloat16(o - __bfloat162float(oh));
        }
    }
    if (tc == 31) finals[b * HD + h] = hcur;
}

// ---------------------------------------------------------------------------
extern "C" void kernel_launch(void* const* d_in, const int* in_sizes, int n_in,
                              void* d_out, int out_size)
{
    const float* x  = (const float*)d_in[0];
    const float* h  = (const float*)d_in[1];
    const float* W0 = (const float*)d_in[2];
    const float* b0 = (const float*)d_in[3];
    const float* Wl = (const float*)d_in[4];
    const float* bl = (const float*)d_in[5];

    float* out    = (float*)d_out;
    float* finals = out + (size_t)MD * HD;

    float *gh, *o0, *o1;
    __nv_bfloat16 *xh, *xl, *wh, *wl;
    cudaGetSymbolAddress((void**)&gh, g_gh);
    cudaGetSymbolAddress((void**)&o0, g_o0);
    cudaGetSymbolAddress((void**)&o1, g_o1);
    cudaGetSymbolAddress((void**)&xh, g_xh);
    cudaGetSymbolAddress((void**)&xl, g_xl);
    cudaGetSymbolAddress((void**)&wh, g_wh);
    cudaGetSymbolAddress((void**)&wl, g_wl);

    cudaFuncSetAttribute(gemm_mma, cudaFuncAttributeMaxDynamicSharedMemorySize,
                         SMEM_TOTAL);

    conv_w<<<512, 256>>>(W0, Wl, wh, wl);
    conv_split<<<1024, 256>>>(x, xh, xl, (size_t)MD * DD);

    const dim3 ggrid(ED / N_TILE, MD / M_TILE);   // (8, 128)
    const dim3 sgrid(HD / 32, BD);                // (32, 8)

    const float* inp = x;
    for (int l = 0; l < LAYERS; l++) {
        const size_t woff = (size_t)l * ED * DD;
        const float* bb = (l == 0) ? b0 : bl + (size_t)(l - 1) * ED;
        float* o = (l == LAYERS - 1) ? out : ((l & 1) ? o1 : o0);
        const int do_split = (l < LAYERS - 1);

        gemm_mma<<<ggrid, 256, SMEM_TOTAL>>>(xh, xl, wh + woff, wl + woff, bb, gh);
        scan_split_k<<<sgrid, 1024>>>(gh, inp, h + (size_t)l * BD * HD, o,
                                      xh, xl, finals + (size_t)l * BD * HD, do_split);
        inp = o;
    }
}

// round 6
// speedup vs baseline: 5.1794x; 1.8557x over previous
#include <cuda_runtime.h>
#include <cuda_fp16.h>
#include <cstdint>

#define BD 8
#define SD 2048
#define DD 1024
#define HD 1024
#define ED 2048
#define MD (BD * SD)
#define LAYERS 4

#define M_TILE 128
#define N_TILE 256
#define K_CHUNK 32
#define NCHUNK (DD / K_CHUNK)     // 32

#define ROW_B 80                  // 64B data + 16B pad: conflict-free LDSM
#define A_TILE_B (128 * ROW_B)    // 10240
#define W_TILE_B (256 * ROW_B)    // 20480
#define A_OFF 0
#define W_OFF A_TILE_B
#define STAGE_B (A_TILE_B + W_TILE_B)   // 30720
#define NSTAGE 3
#define SMEM_TOTAL (NSTAGE * STAGE_B)   // 92160

__device__ __half g_gh[(size_t)MD * ED];           // fp16 pre-activations
__device__ float  g_o0[(size_t)MD * HD];
__device__ float  g_o1[(size_t)MD * HD];
__device__ __half g_xh[(size_t)MD * DD];           // fp16 activations (GEMM A)
__device__ __half g_wh[(size_t)LAYERS * ED * DD];  // fp16 weights

__device__ __forceinline__ uint32_t smem_u32(const void* p) {
    uint32_t a;
    asm("{ .reg .u64 t; cvta.to.shared.u64 t, %1; cvt.u32.u64 %0, t; }"
        : "=r"(a) : "l"(p));
    return a;
}
__device__ __forceinline__ void cp16(uint32_t dst, const void* src) {
    asm volatile("cp.async.cg.shared.global [%0], [%1], 16;" :: "r"(dst), "l"(src));
}
__device__ __forceinline__ void ldsm4(uint32_t* r, uint32_t addr) {
    asm volatile("ldmatrix.sync.aligned.m8n8.x4.shared.b16 {%0,%1,%2,%3}, [%4];"
                 : "=r"(r[0]), "=r"(r[1]), "=r"(r[2]), "=r"(r[3]) : "r"(addr));
}
__device__ __forceinline__ void mma16816(float* c, const uint32_t* a,
                                         uint32_t b0, uint32_t b1) {
    asm volatile(
        "mma.sync.aligned.m16n8k16.row.col.f32.f16.f16.f32 "
        "{%0,%1,%2,%3}, {%4,%5,%6,%7}, {%8,%9}, {%0,%1,%2,%3};"
        : "+f"(c[0]), "+f"(c[1]), "+f"(c[2]), "+f"(c[3])
        : "r"(a[0]), "r"(a[1]), "r"(a[2]), "r"(a[3]), "r"(b0), "r"(b1));
}

// ---------------------------------------------------------------------------
// GEMM: gh[m,n] = fp16( sum_k A[m,k]*W[n,k] + bias[n] )  (fp16 in, fp32 acc)
// CTA 128x256, 8 warps (2x4), warp tile 64x64, 3-stage cp.async ring.
// ---------------------------------------------------------------------------
__global__ __launch_bounds__(256, 1) void gemm_mma(
    const __half* __restrict__ A, const __half* __restrict__ W,
    const float* __restrict__ bias, __half* __restrict__ C)
{
    extern __shared__ char smem[];
    const uint32_t sbase = smem_u32(smem);
    const int tid  = threadIdx.x;
    const int wid  = tid >> 5;
    const int lane = tid & 31;
    const int g    = lane >> 2;
    const int t4   = lane & 3;
    const int wm   = wid >> 2;        // 0..1 : 64 m-rows
    const int wn   = wid & 3;         // 0..3 : 64 n-cols
    const int bm   = blockIdx.y * M_TILE;
    const int bn   = blockIdx.x * N_TILE;

    float acc[4][8][4];
#pragma unroll
    for (int i = 0; i < 4; i++)
#pragma unroll
        for (int j = 0; j < 8; j++)
#pragma unroll
            for (int q = 0; q < 4; q++) acc[i][j][q] = 0.f;

    auto fill = [&](int s, int c) {
        const uint32_t st = sbase + s * STAGE_B;
        const int k0 = c * K_CHUNK;
#pragma unroll
        for (int rep = 0; rep < 2; rep++) {          // A: 128 rows x 4 chunks
            const int v  = tid + rep * 256;
            const int r  = v >> 2, c4 = v & 3;
            cp16(st + A_OFF + r * ROW_B + c4 * 16,
                 A + (size_t)(bm + r) * DD + k0 + c4 * 8);
        }
#pragma unroll
        for (int rep = 0; rep < 4; rep++) {          // W: 256 rows x 4 chunks
            const int v  = tid + rep * 256;
            const int r  = v >> 2, c4 = v & 3;
            cp16(st + W_OFF + r * ROW_B + c4 * 16,
                 W + (size_t)(bn + r) * DD + k0 + c4 * 8);
        }
        asm volatile("cp.async.commit_group;" ::: "memory");
    };

    const uint32_t a_off = (uint32_t)(wm * 64 + (lane & 15)) * ROW_B
                         + ((lane >> 4) & 1) * 16;
    const uint32_t w_mi  = (uint32_t)(lane >> 3);
    const uint32_t w_off = (uint32_t)(wn * 64 + (w_mi >> 1) * 8 + (lane & 7)) * ROW_B
                         + (w_mi & 1) * 16;

    fill(0, 0);
    fill(1, 1);

#pragma unroll 1
    for (int c = 0; c < NCHUNK; c++) {
        if (c + 1 < NCHUNK)
            asm volatile("cp.async.wait_group 1;" ::: "memory");
        else
            asm volatile("cp.async.wait_group 0;" ::: "memory");
        __syncthreads();

        if (c + 2 < NCHUNK) fill((c + 2) % NSTAGE, c + 2);

        const uint32_t st = sbase + (c % NSTAGE) * STAGE_B;
#pragma unroll
        for (int k16 = 0; k16 < 2; k16++) {
            const uint32_t kb = (uint32_t)k16 * 32;
            uint32_t wf[4][4];
#pragma unroll
            for (int jp = 0; jp < 4; jp++)
                ldsm4(wf[jp], st + W_OFF + w_off + jp * (16 * ROW_B) + kb);
#pragma unroll
            for (int mi = 0; mi < 4; mi++) {
                uint32_t af[4];
                ldsm4(af, st + A_OFF + a_off + mi * (16 * ROW_B) + kb);
#pragma unroll
                for (int jp = 0; jp < 4; jp++) {
                    mma16816(acc[mi][jp * 2],     af, wf[jp][0], wf[jp][1]);
                    mma16816(acc[mi][jp * 2 + 1], af, wf[jp][2], wf[jp][3]);
                }
            }
        }
    }

    // epilogue: bias + fp16 (half2) stores
    float bj[8][2];
#pragma unroll
    for (int j = 0; j < 8; j++) {
        const int col = bn + wn * 64 + j * 8 + 2 * t4;
        bj[j][0] = bias[col]; bj[j][1] = bias[col + 1];
    }
#pragma unroll
    for (int mi = 0; mi < 4; mi++) {
        const int r0 = bm + wm * 64 + mi * 16 + g;
#pragma unroll
        for (int j = 0; j < 8; j++) {
            const int col = bn + wn * 64 + j * 8 + 2 * t4;
            __half2 v0 = __floats2half2_rn(acc[mi][j][0] + bj[j][0],
                                           acc[mi][j][1] + bj[j][1]);
            __half2 v1 = __floats2half2_rn(acc[mi][j][2] + bj[j][0],
                                           acc[mi][j][3] + bj[j][1]);
            *(__half2*)(C + (size_t)r0 * ED + col)       = v0;
            *(__half2*)(C + (size_t)(r0 + 8) * ED + col) = v1;
        }
    }
}

// ---------------------------------------------------------------------------
__global__ __launch_bounds__(256) void conv_x(
    const float* __restrict__ src, __half* __restrict__ dst, size_t n)
{
    for (size_t i = (size_t)blockIdx.x * blockDim.x + threadIdx.x; i < n;
         i += (size_t)gridDim.x * blockDim.x)
        dst[i] = __float2half_rn(src[i]);
}

__global__ __launch_bounds__(256) void conv_w(
    const float* __restrict__ W0, const float* __restrict__ Wl,
    __half* __restrict__ dst)
{
    const size_t per = (size_t)ED * DD;
    const size_t n = (size_t)LAYERS * per;
    for (size_t i = (size_t)blockIdx.x * blockDim.x + threadIdx.x; i < n;
         i += (size_t)gridDim.x * blockDim.x)
        dst[i] = __float2half_rn((i < per) ? W0[i] : Wl[i - per]);
}

// ---------------------------------------------------------------------------
// Scan: h_t = (1-z) h_{t-1} + z g(hid); out = h + inp (fp32) ; next A (fp16).
// ---------------------------------------------------------------------------
__device__ __forceinline__ float sigf(float x) { return 1.f / (1.f + __expf(-x)); }

__global__ __launch_bounds__(1024) void scan_k(
    const __half* __restrict__ gh, const float* __restrict__ inp,
    const float* __restrict__ h0, float* __restrict__ outp,
    __half* __restrict__ outa, float* __restrict__ finals, int do_a)
{
    const int b  = blockIdx.y;
    const int hx = threadIdx.x & 31;
    const int tc = threadIdx.x >> 5;
    const int h  = blockIdx.x * 32 + hx;
    const int CH = SD / 32;
    const int t0 = tc * CH;

    const size_t rowbase = (size_t)b * SD;
    const __half* gp = gh + rowbase * ED + h;
    const __half* hp = gp + HD;

    float Ac = 1.f, Cc = 0.f;
#pragma unroll 4
    for (int j = 0; j < CH; j++) {
        const size_t off = (size_t)(t0 + j) * ED;
        const float z = sigf(__half2float(gp[off]));
        const float hid = __half2float(hp[off]);
        const float gg = (hid >= 0.f) ? (hid + 0.5f) : sigf(hid);
        const float a = 1.f - z;
        Cc = fmaf(a, Cc, z * gg);
        Ac *= a;
    }

    __shared__ float sA[32][33], sC[32][33];
    sA[tc][hx] = Ac; sC[tc][hx] = Cc;
    __syncthreads();

    const float hprev = h0[b * HD + h];
    float hcur = (hprev >= 0.f) ? (hprev + 0.5f) : sigf(hprev);
    for (int c = 0; c < tc; c++) hcur = fmaf(sA[c][hx], hcur, sC[c][hx]);

    const size_t obase = rowbase * HD + h;
    const float* ip = inp + obase;
    float* op = outp + obase;
#pragma unroll 4
    for (int j = 0; j < CH; j++) {
        const size_t off = (size_t)(t0 + j) * ED;
        const float z = sigf(__half2float(gp[off]));
        const float hid = __half2float(hp[off]);
        const float gg = (hid >= 0.f) ? (hid + 0.5f) : sigf(hid);
        hcur = fmaf(1.f - z, hcur, z * gg);
        const size_t o2 = (size_t)(t0 + j) * HD;
        const float o = hcur + ip[o2];
        op[o2] = o;
        if (do_a) outa[obase + o2] = __float2half_rn(o);
    }
    if (tc == 31) finals[b * HD + h] = hcur;
}

// ---------------------------------------------------------------------------
extern "C" void kernel_launch(void* const* d_in, const int* in_sizes, int n_in,
                              void* d_out, int out_size)
{
    const float* x  = (const float*)d_in[0];
    const float* h  = (const float*)d_in[1];
    const float* W0 = (const float*)d_in[2];
    const float* b0 = (const float*)d_in[3];
    const float* Wl = (const float*)d_in[4];
    const float* bl = (const float*)d_in[5];

    float* out    = (float*)d_out;
    float* finals = out + (size_t)MD * HD;

    __half *gh, *xh, *wh;
    float *o0, *o1;
    cudaGetSymbolAddress((void**)&gh, g_gh);
    cudaGetSymbolAddress((void**)&o0, g_o0);
    cudaGetSymbolAddress((void**)&o1, g_o1);
    cudaGetSymbolAddress((void**)&xh, g_xh);
    cudaGetSymbolAddress((void**)&wh, g_wh);

    cudaFuncSetAttribute(gemm_mma, cudaFuncAttributeMaxDynamicSharedMemorySize,
                         SMEM_TOTAL);

    conv_w<<<512, 256>>>(W0, Wl, wh);
    conv_x<<<512, 256>>>(x, xh, (size_t)MD * DD);

    const dim3 ggrid(ED / N_TILE, MD / M_TILE);   // (8, 128)
    const dim3 sgrid(HD / 32, BD);                // (32, 8)

    const float* inp = x;
    for (int l = 0; l < LAYERS; l++) {
        const size_t woff = (size_t)l * ED * DD;
        const float* bb = (l == 0) ? b0 : bl + (size_t)(l - 1) * ED;
        float* o = (l == LAYERS - 1) ? out : ((l & 1) ? o1 : o0);
        const int do_a = (l < LAYERS - 1);

        gemm_mma<<<ggrid, 256, SMEM_TOTAL>>>(xh, wh + woff, bb, gh);
        scan_k<<<sgrid, 1024>>>(gh, inp, h + (size_t)l * BD * HD, o,
                                xh, finals + (size_t)l * BD * HD, do_a);
        inp = o;
    }
}